// round 12
// baseline (speedup 1.0000x reference)
#include <cuda_runtime.h>
#include <math.h>
#include <stdint.h>

#define Bz  2
#define Tt  2048
#define Cc  2048
#define NH  32
#define NKV 8
#define HD  64
#define KVD (NKV * HD)   /* 512 */
#define BT  (Bz * Tt)    /* 4096 */

// Scratch (allocation-free rule: __device__ globals)
__device__ float g_q[(size_t)BT * Cc];
__device__ float g_k[(size_t)BT * KVD];
__device__ float g_v[(size_t)BT * KVD];
__device__ float g_attn[(size_t)BT * Cc];

// ---------------------------------------------------------------------------
// helpers
// ---------------------------------------------------------------------------
__device__ __forceinline__ float to_tf32(float x) {
    uint32_t r;
    asm("cvt.rna.tf32.f32 %0, %1;" : "=r"(r) : "f"(x));
    return __uint_as_float(r);
}
__device__ __forceinline__ float4 to_tf32_4(float4 v) {
    return make_float4(to_tf32(v.x), to_tf32(v.y), to_tf32(v.z), to_tf32(v.w));
}
__device__ __forceinline__ float4 to_tf32_4s(float4 v, float s) {
    return make_float4(to_tf32(v.x * s), to_tf32(v.y * s),
                       to_tf32(v.z * s), to_tf32(v.w * s));
}
__device__ __forceinline__ float ex2f(float x) {
    float r;
    asm("ex2.approx.f32 %0, %1;" : "=f"(r) : "f"(x));
    return r;
}

// Named barriers (ids 1..4; id 0 belongs to __syncthreads).
// Pattern per round: 256 threads bar.arrive + 256 threads bar.sync = 512.
#define BARN_SYNC(id)   asm volatile("bar.sync %0, 512;"   :: "r"(id) : "memory")
#define BARN_ARRIVE(id) asm volatile("bar.arrive %0, 512;" :: "r"(id) : "memory")

// D = A(16x8,row) @ B(8x8,col) + D, tf32 inputs (as b32), fp32 accum.
__device__ __forceinline__ void mma8(float c[4], const uint32_t a[4],
                                     uint32_t b0, uint32_t b1) {
    asm("mma.sync.aligned.m16n8k8.row.col.f32.tf32.tf32.f32 "
        "{%0,%1,%2,%3}, {%4,%5,%6,%7}, {%8,%9}, {%0,%1,%2,%3};\n"
        : "+f"(c[0]), "+f"(c[1]), "+f"(c[2]), "+f"(c[3])
        : "r"(a[0]), "r"(a[1]), "r"(a[2]), "r"(a[3]), "r"(b0), "r"(b1));
}

// ldmatrix x4 on 32-bit data (each 8x4-float quadrant viewed as 8x16B b16 mat).
__device__ __forceinline__ void ldsm4(uint32_t f[4], const float* p) {
    uint32_t a = (uint32_t)__cvta_generic_to_shared(p);
    asm("ldmatrix.sync.aligned.m8n8.x4.shared.b16 {%0,%1,%2,%3}, [%4];"
        : "=r"(f[0]), "=r"(f[1]), "=r"(f[2]), "=r"(f[3]) : "r"(a));
}
// A-pattern: f0=(g,t) f1=(g+8,t) f2=(g,t+4) f3=(g+8,t+4)  == mma A frag
#define AOFF(lane, S) (((((lane) >> 3) & 1) * 8 + ((lane) & 7)) * (S) + ((lane) >> 4) * 4)
// B-pattern: f0=b0(nt) f1=b1(nt) f2=b0(nt+1) f3=b1(nt+1)
#define BOFF(lane, S) ((((lane) >> 4) * 8 + ((lane) & 7)) * (S) + (((lane) >> 3) & 1) * 4)

// ---------------------------------------------------------------------------
// mma.sync tf32 GEMM, double-buffered, LDSM fragment loads. (unchanged)
// CTA tile 256x128, BK=32, 256 threads (8 warps), warp grid 4(M)x2(N),
// warp tile 64x64. Two SMEM stages, one barrier per chunk.
// ---------------------------------------------------------------------------
#define GP 36
#define SMEM_GEMM ((2 * 256 + 2 * 128) * GP * 4)   /* 110592 B */

__global__ __launch_bounds__(256, 1) void gemm_mma(
    const float* __restrict__ A,
    const float* __restrict__ B0, float* __restrict__ C0,
    const float* __restrict__ B1, float* __restrict__ C1,
    int N, int K)
{
    extern __shared__ float sm[];
    float* As = sm;                    // [2][256][GP]
    float* Bs = sm + 2 * 256 * GP;     // [2][128][GP]

    const float* B = blockIdx.z ? B1 : B0;
    float*       C = blockIdx.z ? C1 : C0;

    const int tid  = threadIdx.x;
    const int wid  = tid >> 5;
    const int lane = tid & 31;
    const int gid  = lane >> 2;
    const int tig  = lane & 3;
    const int wm   = wid & 3;          // m base 64*wm
    const int wn   = wid >> 2;         // n base 64*wn
    const int aoff = AOFF(lane, GP);
    const int boff = BOFF(lane, GP);

    const float* Ab = A + (size_t)blockIdx.y * 256 * K;
    const float* Bb = B + (size_t)blockIdx.x * 128;

    const int bk = tid & 31, bn = (tid >> 5) * 16;

    float acc[4][8][4];
#pragma unroll
    for (int i = 0; i < 4; i++)
#pragma unroll
        for (int j = 0; j < 8; j++)
#pragma unroll
            for (int e = 0; e < 4; e++) acc[i][j][e] = 0.f;

    float4 a4[8], b4[4];
    const int NC = K >> 5;

#define LDG_A(k0)                                                              \
    do {                                                                       \
        const float* ap = Ab + (size_t)tid * K + (k0);                         \
        _Pragma("unroll")                                                      \
        for (int j = 0; j < 8; j++) a4[j] = *(const float4*)(ap + 4 * j);      \
    } while (0)

#define LDG_B(k0)                                                              \
    do {                                                                       \
        const float* bp = Bb + (size_t)((k0) + bk) * N + bn;                   \
        _Pragma("unroll")                                                      \
        for (int j = 0; j < 4; j++) b4[j] = *(const float4*)(bp + 4 * j);      \
    } while (0)

#define STS_A(st)                                                              \
    do {                                                                       \
        float* ad = As + ((st) * 256 + tid) * GP;                              \
        _Pragma("unroll")                                                      \
        for (int j = 0; j < 8; j++)                                            \
            *(float4*)(ad + 4 * j) = to_tf32_4(a4[j]);                         \
    } while (0)

#define STS_B(st)                                                              \
    do {                                                                       \
        const float* bf = (const float*)b4;                                    \
        _Pragma("unroll")                                                      \
        for (int e = 0; e < 16; e++)                                           \
            Bs[((st) * 128 + bn + e) * GP + bk] = to_tf32(bf[e]);              \
    } while (0)

#define COMPUTE_KS(st, ks)                                                     \
    do {                                                                       \
        uint32_t af[4][4], bfr[4][4];                                          \
        const float* Ast = As + (st) * 256 * GP + (ks) * 8;                    \
        const float* Bst = Bs + (st) * 128 * GP + (ks) * 8;                    \
        _Pragma("unroll")                                                      \
        for (int mt = 0; mt < 4; mt++)                                         \
            ldsm4(af[mt], Ast + (wm * 64 + mt * 16) * GP + aoff);              \
        _Pragma("unroll")                                                      \
        for (int np = 0; np < 4; np++)                                         \
            ldsm4(bfr[np], Bst + (wn * 64 + np * 16) * GP + boff);             \
        _Pragma("unroll")                                                      \
        for (int nt = 0; nt < 8; nt++)                                         \
            _Pragma("unroll")                                                  \
            for (int mt = 0; mt < 4; mt++)                                     \
                mma8(acc[mt][nt], af[mt],                                      \
                     bfr[nt >> 1][(nt & 1) * 2], bfr[nt >> 1][(nt & 1) * 2 + 1]); \
    } while (0)

    // prologue
    LDG_A(0); STS_A(0);
    LDG_B(0); STS_B(0);
    __syncthreads();

    for (int c = 0; c < NC; c++) {
        const int st = c & 1;
        const bool more = (c + 1 < NC);
        if (more) LDG_B((c + 1) * 32);
        COMPUTE_KS(st, 0);
        if (more) { STS_B(st ^ 1); LDG_A((c + 1) * 32); }
        COMPUTE_KS(st, 1);
        COMPUTE_KS(st, 2);
        if (more) STS_A(st ^ 1);
        COMPUTE_KS(st, 3);
        __syncthreads();
    }

    float* Cb = C + (size_t)blockIdx.y * 256 * N + blockIdx.x * 128;
#pragma unroll
    for (int mt = 0; mt < 4; mt++) {
        const int r0 = wm * 64 + mt * 16 + gid;
#pragma unroll
        for (int nt = 0; nt < 8; nt++) {
            const int cb = wn * 64 + nt * 8 + 2 * tig;
            *(float2*)(Cb + (size_t)r0 * N + cb) =
                make_float2(acc[mt][nt][0], acc[mt][nt][1]);
            *(float2*)(Cb + (size_t)(r0 + 8) * N + cb) =
                make_float2(acc[mt][nt][2], acc[mt][nt][3]);
        }
    }
}

// ---------------------------------------------------------------------------
// RoPE: one block per token row; 32 (cos,sin) pairs computed once in double.
// ---------------------------------------------------------------------------
__global__ __launch_bounds__(256) void rope2(float* __restrict__ q, float* __restrict__ k)
{
    const int row = blockIdx.x;          // 0..BT-1
    __shared__ float cs[32], sn[32];
    if (threadIdx.x < 32) {
        const int i = threadIdx.x;
        const double freq = exp2(-0.41524101186092028 * (double)i);
        const double ang  = (double)(row & (Tt - 1)) * freq;
        double s, c;
        sincos(ang, &s, &c);
        cs[i] = (float)c; sn[i] = (float)s;
    }
    __syncthreads();

    float2* qr = (float2*)(q + (size_t)row * Cc);
#pragma unroll
    for (int p = threadIdx.x; p < Cc / 2; p += 256) {
        const int i = p & 31;
        float2 v = qr[p];
        qr[p] = make_float2(v.x * cs[i] - v.y * sn[i],
                            v.x * sn[i] + v.y * cs[i]);
    }
    float2* kr = (float2*)(k + (size_t)row * KVD);
    {
        const int p = threadIdx.x;   // KVD/2 = 256 pairs, one per thread
        const int i = p & 31;
        float2 v = kr[p];
        kr[p] = make_float2(v.x * cs[i] - v.y * sn[i],
                            v.x * sn[i] + v.y * cs[i]);
    }
}

// ---------------------------------------------------------------------------
// Flash attention, mma.sync tf32, LDSM, chain-free softmax, and now
// DESYNCHRONIZED WARPS: the per-tile __syncthreads (which phase-locked all
// 8 warps so softmax MUFU bursts and mma bursts alternated chip-wide) is
// replaced by per-stage named-barrier arrive/sync pairs:
//   barW[st] (ids 1,2): readers-of-stage-st done  (WAR gate before STS)
//   barF[st] (ids 3,4): stage-st filled           (RAW gate before reads)
// Each round = 256 arrives + 256 syncs = count 512. A thread cannot start
// round N+1 before passing its own round-N sync, so rounds never mix.
// Warps may drift up to one tile apart -> one warp's ex2/softmax overlaps
// the other warp's S/PV mma on the same SMSP (MUFU floor ~252us and tensor
// floor ~253us can finally run concurrently).
// Numerics identical to previous round.
// ---------------------------------------------------------------------------
#define QT   256
#define PADA 68
#define SMEM_ATTN ((2 * QT + 4 * 64) * PADA * 4)   /* 208896 B */

__global__ __launch_bounds__(256, 1) void attn_mma(
    const float* __restrict__ Q, const float* __restrict__ K,
    const float* __restrict__ V, float* __restrict__ O)
{
    extern __shared__ float sm[];
    float* Qs = sm;                           // [QT][PADA]
    float* Ps = sm + QT * PADA;               // [QT][PADA]
    float* Ks = sm + 2 * QT * PADA;           // [2][64][PADA]
    float* Vs = Ks + 2 * 64 * PADA;           // [2][64][PADA]

    const int tid  = threadIdx.x;
    const int wid  = tid >> 5;                // 0..7
    const int lane = tid & 31;
    const int gid  = lane >> 2;
    const int tig  = lane & 3;
    const int aoff = AOFF(lane, PADA);
    const int boff = BOFF(lane, PADA);
    const int qtile = blockIdx.x, h = blockIdx.y, b = blockIdx.z;
    const int kvh  = h >> 2;

    const float* qbase = Q + (size_t)(b * Tt + qtile * QT) * Cc + h * HD;
    const float* kbase = K + (size_t)b * Tt * KVD + kvh * HD;
    const float* vbase = V + (size_t)b * Tt * KVD + kvh * HD;

    // stage Q scaled by log2e/8 (S comes out in log2 domain), tf32, STS.128
    {
        const float QSCALE = 1.4426950408889634f * 0.125f;
        const float* src = qbase + (size_t)tid * Cc;
        float* dst = Qs + tid * PADA;
#pragma unroll
        for (int j = 0; j < 16; j++)
            *(float4*)(dst + 4 * j) =
                to_tf32_4s(*(const float4*)(src + 4 * j), QSCALE);
    }

    const int r  = tid & 63;        // K/V row
    const int c0 = (tid >> 6) * 16; // d-chunk (4 chunks of 16)

    float4 k4[4], v4[4];
#define ATTN_LDG(kt)                                                           \
    do {                                                                       \
        const float* ksrc = kbase + (size_t)((kt) * 64 + r) * KVD + c0;        \
        const float* vsrc = vbase + (size_t)((kt) * 64 + r) * KVD + c0;        \
        _Pragma("unroll")                                                      \
        for (int j = 0; j < 4; j++) k4[j] = *(const float4*)(ksrc + 4 * j);    \
        _Pragma("unroll")                                                      \
        for (int j = 0; j < 4; j++) v4[j] = *(const float4*)(vsrc + 4 * j);    \
    } while (0)

#define ATTN_STS(st)                                                           \
    do {                                                                       \
        float* kd = Ks + ((st) * 64 + r) * PADA + c0;                          \
        _Pragma("unroll")                                                      \
        for (int j = 0; j < 4; j++)                                            \
            *(float4*)(kd + 4 * j) = to_tf32_4(k4[j]);                         \
        const float* vf = (const float*)v4;                                    \
        float* vb = Vs + (st) * 64 * PADA;                                     \
        _Pragma("unroll")                                                      \
        for (int e = 0; e < 16; e++)                                           \
            vb[(size_t)(c0 + e) * PADA + r] = to_tf32(vf[e]);                  \
    } while (0)

    // prologue: tile 0 staged into stage 0; visibility via __syncthreads
    ATTN_LDG(0);
    ATTN_STS(0);

    float* Pw = Ps + (size_t)(32 * wid) * PADA;   // warp-private P slice

    float o[2][8][4];
#pragma unroll
    for (int mt = 0; mt < 2; mt++)
#pragma unroll
        for (int nt = 0; nt < 8; nt++)
#pragma unroll
            for (int e = 0; e < 4; e++) o[mt][nt][e] = 0.f;
    float lr[2][2];
#pragma unroll
    for (int mt = 0; mt < 2; mt++) { lr[mt][0] = 0.f; lr[mt][1] = 0.f; }
    __syncthreads();

    for (int kt = 0; kt < Tt / 64; kt++) {
        const int st = kt & 1;
        const bool more = (kt + 1 < Tt / 64);
        const float* Kst = Ks + st * 64 * PADA;
        const float* Vst = Vs + st * 64 * PADA;

        // RAW gate: stage st filled by all warps' STS at tile kt-1
        if (kt > 0) BARN_SYNC(3 + st);

        // S' = (Q*log2e/8) @ K^T  (LDSM operand loads)
        float s[2][8][4];
#pragma unroll
        for (int mt = 0; mt < 2; mt++)
#pragma unroll
            for (int nt = 0; nt < 8; nt++)
#pragma unroll
                for (int e = 0; e < 4; e++) s[mt][nt][e] = 0.f;
#pragma unroll
        for (int ks = 0; ks < 8; ks++) {
            uint32_t qa[2][4], kb[4][4];
            ldsm4(qa[0], Qs + (size_t)(32 * wid)      * PADA + ks * 8 + aoff);
            ldsm4(qa[1], Qs + (size_t)(32 * wid + 16) * PADA + ks * 8 + aoff);
#pragma unroll
            for (int np = 0; np < 4; np++)
                ldsm4(kb[np], Kst + (size_t)(np * 16) * PADA + ks * 8 + boff);
#pragma unroll
            for (int nt = 0; nt < 8; nt++) {
                const uint32_t b0 = kb[nt >> 1][(nt & 1) * 2];
                const uint32_t b1 = kb[nt >> 1][(nt & 1) * 2 + 1];
                mma8(s[0][nt], qa[0], b0, b1);
                mma8(s[1][nt], qa[1], b0, b1);
            }
        }

        // prefetch next tile's K/V (consumed by STS after PV)
        if (more) ATTN_LDG(kt + 1);

        // chain-free softmax numerator: P = 2^S', partial row sums only
#pragma unroll
        for (int mt = 0; mt < 2; mt++) {
            float* Pm = Pw + (size_t)(16 * mt) * PADA;
#pragma unroll
            for (int nt = 0; nt < 8; nt++) {
                const float p0 = ex2f(s[mt][nt][0]);
                const float p1 = ex2f(s[mt][nt][1]);
                const float p2 = ex2f(s[mt][nt][2]);
                const float p3 = ex2f(s[mt][nt][3]);
                lr[mt][0] += p0 + p1;
                lr[mt][1] += p2 + p3;
                const int cb = nt * 8 + 2 * tig;
                *(float2*)(Pm +  gid      * PADA + cb) =
                    make_float2(to_tf32(p0), to_tf32(p1));
                *(float2*)(Pm + (gid + 8) * PADA + cb) =
                    make_float2(to_tf32(p2), to_tf32(p3));
            }
        }
        __syncwarp();      // P visible within the warp

        // O += P @ V  (LDSM operand loads; V B-frags shared across m-tiles)
#pragma unroll
        for (int ks = 0; ks < 8; ks++) {
            uint32_t pa[2][4], vb[4][4];
            ldsm4(pa[0], Pw + ks * 8 + aoff);
            ldsm4(pa[1], Pw + (size_t)16 * PADA + ks * 8 + aoff);
#pragma unroll
            for (int np = 0; np < 4; np++)
                ldsm4(vb[np], Vst + (size_t)(np * 16) * PADA + ks * 8 + boff);
#pragma unroll
            for (int nt = 0; nt < 8; nt++) {
                const uint32_t b0 = vb[nt >> 1][(nt & 1) * 2];
                const uint32_t b1 = vb[nt >> 1][(nt & 1) * 2 + 1];
                mma8(o[0][nt], pa[0], b0, b1);
                mma8(o[1][nt], pa[1], b0, b1);
            }
        }

        // this warp is done READING stage st
        BARN_ARRIVE(1 + st);

        if (more) {
            // WAR gate: all readers of stage st^1 (tile kt-1) done
            if (kt > 0) BARN_SYNC(1 + (st ^ 1));
            ATTN_STS(st ^ 1);
            // stage st^1 now filled by this thread
            BARN_ARRIVE(3 + (st ^ 1));
        }
    }

    // one-time row-sum reduction across the 4 tig lanes
#pragma unroll
    for (int mt = 0; mt < 2; mt++)
#pragma unroll
        for (int i = 0; i < 2; i++) {
            lr[mt][i] += __shfl_xor_sync(0xffffffffu, lr[mt][i], 1);
            lr[mt][i] += __shfl_xor_sync(0xffffffffu, lr[mt][i], 2);
        }

    // write O
#pragma unroll
    for (int mt = 0; mt < 2; mt++) {
        const float inv0 = 1.f / lr[mt][0], inv1 = 1.f / lr[mt][1];
        const size_t q0 = (size_t)(b * Tt + qtile * QT + 32 * wid + 16 * mt + gid);
#pragma unroll
        for (int nt = 0; nt < 8; nt++) {
            const int cb = h * HD + nt * 8 + 2 * tig;
            *(float2*)(O +  q0      * Cc + cb) =
                make_float2(o[mt][nt][0] * inv0, o[mt][nt][1] * inv0);
            *(float2*)(O + (q0 + 8) * Cc + cb) =
                make_float2(o[mt][nt][2] * inv1, o[mt][nt][3] * inv1);
        }
    }
}

// ---------------------------------------------------------------------------
extern "C" void kernel_launch(void* const* d_in, const int* in_sizes, int n_in,
                              void* d_out, int out_size)
{
    const float* x  = (const float*)d_in[0];
    const float* wq = (const float*)d_in[1];
    const float* wk = (const float*)d_in[2];
    const float* wv = (const float*)d_in[3];
    const float* wo = (const float*)d_in[4];
    float* out = (float*)d_out;

    float *qp, *kp, *vp, *ap;
    cudaGetSymbolAddress((void**)&qp, g_q);
    cudaGetSymbolAddress((void**)&kp, g_k);
    cudaGetSymbolAddress((void**)&vp, g_v);
    cudaGetSymbolAddress((void**)&ap, g_attn);

    cudaFuncSetAttribute(gemm_mma, cudaFuncAttributeMaxDynamicSharedMemorySize,
                         SMEM_GEMM);
    cudaFuncSetAttribute(attn_mma, cudaFuncAttributeMaxDynamicSharedMemorySize,
                         SMEM_ATTN);

    // Q projection (256x128 CTA tiles)
    gemm_mma<<<dim3(Cc / 128, BT / 256, 1), 256, SMEM_GEMM>>>(
        x, wq, qp, wq, qp, Cc, Cc);
    // K + V projections fused into one full-chip launch (z selects pair)
    gemm_mma<<<dim3(KVD / 128, BT / 256, 2), 256, SMEM_GEMM>>>(
        x, wk, kp, wv, vp, KVD, Cc);

    // RoPE on q and k
    rope2<<<BT, 256>>>(qp, kp);

    // Attention (LDSM, chain-free softmax, desynchronized warps)
    attn_mma<<<dim3(Tt / QT, NH, Bz), 256, SMEM_ATTN>>>(qp, kp, vp, ap);

    // Output projection
    gemm_mma<<<dim3(Cc / 128, BT / 256, 1), 256, SMEM_GEMM>>>(
        ap, wo, out, wo, out, Cc, Cc);
}